// round 14
// baseline (speedup 1.0000x reference)
#include <cuda_runtime.h>
#include <cuda_bf16.h>
#include <mma.h>
#include <cstdint>

#define NPTS 65536
#define HN 32
#define CIN 256
#define CMID 64
#define COUT 256
#define KP 15
#define SLOPE 0.1f
#define EPSV 1e-5f

using ull = unsigned long long;
using namespace nvcuda;

// ---- packed f32x2 helpers ----
__device__ __forceinline__ ull pk2(float lo, float hi) {
    ull r; asm("mov.b64 %0, {%1,%2};" : "=l"(r) : "f"(lo), "f"(hi)); return r;
}
__device__ __forceinline__ ull dup2(float v) { return pk2(v, v); }
__device__ __forceinline__ void fma2(ull& d, ull a, ull b) {
    asm("fma.rn.f32x2 %0, %1, %2, %3;" : "=l"(d) : "l"(a), "l"(b), "l"(d));
}
__device__ __forceinline__ float2 up2(ull v) {
    float lo, hi; asm("mov.b64 {%0,%1}, %2;" : "=f"(lo), "=f"(hi) : "l"(v));
    return make_float2(lo, hi);
}

// ---- cp.async helpers ----
__device__ __forceinline__ void cp16(void* sdst, const void* gsrc) {
    uint32_t s = (uint32_t)__cvta_generic_to_shared(sdst);
    asm volatile("cp.async.cg.shared.global [%0], [%1], 16;" :: "r"(s), "l"(gsrc));
}
#define CP_COMMIT() asm volatile("cp.async.commit_group;" ::: "memory")
#define CP_WAIT(n)  asm volatile("cp.async.wait_group %0;" :: "n"(n) : "memory")

// ---- hi/lo split helper ----
__device__ __forceinline__ void split2(float x, float y, uint32_t& h, uint32_t& l) {
    __nv_bfloat162 hh = __floats2bfloat162_rn(x, y);
    __nv_bfloat162 ll = __floats2bfloat162_rn(x - __bfloat162float(hh.x),
                                              y - __bfloat162float(hh.y));
    h = *(uint32_t*)&hh;
    l = *(uint32_t*)&ll;
}

// ---- scratch (device globals; aligned for vector-cast access) ----
__device__ __align__(256) float g_x1[NPTS * CMID];            // 16 MB
__device__ __align__(256) float g_out2[NPTS * CMID];          // 16 MB
__device__ __align__(256) float g_y[NPTS * COUT];             // 64 MB
__device__ __align__(256) __nv_bfloat16 g_Ahi[NPTS * 960];    // 126 MB
__device__ __align__(256) __nv_bfloat16 g_Alo[NPTS * 960];    // 126 MB
__device__ __align__(256) __nv_bfloat16 g_BhiT[64 * 960];
__device__ __align__(256) __nv_bfloat16 g_BloT[64 * 960];
__device__ float g_nnr[NPTS];
__device__ double g_sum1[CMID], g_sq1[CMID];
__device__ double g_sum2[CMID], g_sq2[CMID];
__device__ double g_sum3[COUT], g_sq3[COUT];

// ---- k_prep: zero stats (block 0) + kw transpose/split ----
__global__ __launch_bounds__(256) void k_prep(const float* __restrict__ kw) {
    int t = threadIdx.x;
    if (blockIdx.x == 0) {
        if (t < CMID) { g_sum1[t] = 0.0; g_sq1[t] = 0.0; g_sum2[t] = 0.0; g_sq2[t] = 0.0; }
        if (t < COUT) { g_sum3[t] = 0.0; g_sq3[t] = 0.0; }
    }
    int idx = blockIdx.x * 256 + t;
    int d = idx / 960;
    int r = idx % 960;
    float v = kw[r * 64 + d];
    __nv_bfloat16 h = __float2bfloat16(v);
    g_BhiT[d * 960 + r] = h;
    g_BloT[d * 960 + r] = __float2bfloat16(v - __bfloat162float(h));
}

// ---- GEMM1 (WMMA bf16 hi/lo): x1 = s_feats @ W1 + b1 ; GN1 stats ----
#define G1S 72
#define G1_SMEM (55296 + 512)

__global__ __launch_bounds__(256) void k_gemm1(const float* __restrict__ A,
                                               const float* __restrict__ W,
                                               const float* __restrict__ bias) {
    extern __shared__ __nv_bfloat16 sb1[];
    __nv_bfloat16* sAhi = sb1;
    __nv_bfloat16* sAlo = sb1 + 9216;
    __nv_bfloat16* sBhi = sb1 + 18432;
    __nv_bfloat16* sBlo = sb1 + 23040;
    float* s_stats = (float*)(sb1 + 27648);
    float* sOut = (float*)sb1;

    int t = threadIdx.x;
    int warp = t >> 5;
    int wr = warp >> 1, wc = warp & 1;
    int row0 = blockIdx.x * 128;
    if (t < 128) s_stats[t] = 0.f;

    wmma::fragment<wmma::accumulator, 16, 16, 16, float> acc[2][2];
#pragma unroll
    for (int i = 0; i < 2; i++)
#pragma unroll
        for (int j = 0; j < 2; j++) wmma::fill_fragment(acc[i][j], 0.0f);

    for (int ch = 0; ch < 4; ch++) {
        __syncthreads();
#pragma unroll
        for (int i = 0; i < 8; i++) {
            int e = t + i * 256;
            int r = e >> 4, j = e & 15;
            float4 v = *(const float4*)&A[(size_t)(row0 + r) * CIN + ch * 64 + j * 4];
            uint32_t h0, l0, h1, l1;
            split2(v.x, v.y, h0, l0);
            split2(v.z, v.w, h1, l1);
            *(uint2*)&sAhi[r * G1S + j * 4] = make_uint2(h0, h1);
            *(uint2*)&sAlo[r * G1S + j * 4] = make_uint2(l0, l1);
        }
#pragma unroll
        for (int i = 0; i < 4; i++) {
            int e = t + i * 256;
            int r = e >> 4, j = e & 15;
            float4 v = *(const float4*)&W[(size_t)(ch * 64 + r) * CMID + j * 4];
            uint32_t h0, l0, h1, l1;
            split2(v.x, v.y, h0, l0);
            split2(v.z, v.w, h1, l1);
            *(uint2*)&sBhi[r * G1S + j * 4] = make_uint2(h0, h1);
            *(uint2*)&sBlo[r * G1S + j * 4] = make_uint2(l0, l1);
        }
        __syncthreads();

#pragma unroll
        for (int kk = 0; kk < 4; kk++) {
            wmma::fragment<wmma::matrix_a, 16, 16, 16, __nv_bfloat16, wmma::row_major> a_hi[2], a_lo[2];
            wmma::fragment<wmma::matrix_b, 16, 16, 16, __nv_bfloat16, wmma::row_major> b_hi[2], b_lo[2];
#pragma unroll
            for (int i = 0; i < 2; i++) {
                wmma::load_matrix_sync(a_hi[i], &sAhi[(wr * 32 + i * 16) * G1S + kk * 16], G1S);
                wmma::load_matrix_sync(a_lo[i], &sAlo[(wr * 32 + i * 16) * G1S + kk * 16], G1S);
            }
#pragma unroll
            for (int j = 0; j < 2; j++) {
                wmma::load_matrix_sync(b_hi[j], &sBhi[(kk * 16) * G1S + wc * 32 + j * 16], G1S);
                wmma::load_matrix_sync(b_lo[j], &sBlo[(kk * 16) * G1S + wc * 32 + j * 16], G1S);
            }
#pragma unroll
            for (int i = 0; i < 2; i++)
#pragma unroll
                for (int j = 0; j < 2; j++) {
                    wmma::mma_sync(acc[i][j], a_hi[i], b_hi[j], acc[i][j]);
                    wmma::mma_sync(acc[i][j], a_lo[i], b_hi[j], acc[i][j]);
                    wmma::mma_sync(acc[i][j], a_hi[i], b_lo[j], acc[i][j]);
                }
        }
    }

    __syncthreads();
#pragma unroll
    for (int i = 0; i < 2; i++)
#pragma unroll
        for (int j = 0; j < 2; j++)
            wmma::store_matrix_sync(&sOut[(wr * 32 + i * 16) * G1S + wc * 32 + j * 16],
                                    acc[i][j], G1S, wmma::mem_row_major);
    __syncthreads();

    {
        int c4 = t & 15;
        float b0 = bias[c4 * 4 + 0], b1 = bias[c4 * 4 + 1];
        float b2 = bias[c4 * 4 + 2], b3 = bias[c4 * 4 + 3];
        float cs[4] = {0, 0, 0, 0}, cq[4] = {0, 0, 0, 0};
#pragma unroll
        for (int i = 0; i < 8; i++) {
            int r = (t >> 4) + i * 16;
            float4 v = *(const float4*)&sOut[r * G1S + c4 * 4];
            v.x += b0; v.y += b1; v.z += b2; v.w += b3;
            *(float4*)&g_x1[(size_t)(row0 + r) * CMID + c4 * 4] = v;
            cs[0] += v.x; cq[0] += v.x * v.x;
            cs[1] += v.y; cq[1] += v.y * v.y;
            cs[2] += v.z; cq[2] += v.z * v.z;
            cs[3] += v.w; cq[3] += v.w * v.w;
        }
#pragma unroll
        for (int j = 0; j < 4; j++) {
            atomicAdd(&s_stats[c4 * 4 + j], cs[j]);
            atomicAdd(&s_stats[64 + c4 * 4 + j], cq[j]);
        }
    }
    __syncthreads();
    if (t < 64) {
        atomicAdd(&g_sum1[t], (double)s_stats[t]);
        atomicAdd(&g_sq1[t], (double)s_stats[64 + t]);
    }
}

// ---- k_apply1: GN1 + leaky in place on x1 (inline stat finalize, MLP-4) ----
__global__ __launch_bounds__(256) void k_apply1(const float* __restrict__ gamma,
                                                const float* __restrict__ beta) {
    __shared__ float s_a[64], s_b[64];
    int t = threadIdx.x;
    if (t < 64) {
        int g = t >> 1;
        double s = g_sum1[g * 2] + g_sum1[g * 2 + 1];
        double q = g_sq1[g * 2] + g_sq1[g * 2 + 1];
        double cnt = 2.0 * (double)NPTS;
        double mean = s / cnt;
        double var = q / cnt - mean * mean;
        float inv = rsqrtf((float)var + EPSV);
        float av = gamma[t] * inv;
        s_a[t] = av;
        s_b[t] = beta[t] - (float)mean * av;
    }
    __syncthreads();
    int base = blockIdx.x * 1024 + t;
    int c = (base & 15) * 4;
    float a0 = s_a[c + 0], a1 = s_a[c + 1], a2 = s_a[c + 2], a3 = s_a[c + 3];
    float b0 = s_b[c + 0], b1 = s_b[c + 1], b2 = s_b[c + 2], b3 = s_b[c + 3];
    float4 v[4];
#pragma unroll
    for (int u = 0; u < 4; u++) v[u] = ((const float4*)g_x1)[base + u * 256];
#pragma unroll
    for (int u = 0; u < 4; u++) {
        float4 r;
        r.x = a0 * v[u].x + b0;
        r.y = a1 * v[u].y + b1;
        r.z = a2 * v[u].z + b2;
        r.w = a3 * v[u].w + b3;
        r.x = r.x >= 0.f ? r.x : SLOPE * r.x;
        r.y = r.y >= 0.f ? r.y : SLOPE * r.y;
        r.z = r.z >= 0.f ? r.z : SLOPE * r.z;
        r.w = r.w >= 0.f ? r.w : SLOPE * r.w;
        ((float4*)g_x1)[base + u * 256] = r;
    }
}

// ---- k_gather: 16 points/block, 2 points/warp, 4 ch/lane ----
// s_w layout: (p*32+h)*16 + p*8 (skew keeps the two points of a warp in disjoint banks)
__global__ __launch_bounds__(256, 2) void k_gather(
        const float* __restrict__ qp, const float* __restrict__ sp,
        const int* __restrict__ nbr, const float* __restrict__ kpts) {
    __shared__ float s_kp[48];
    __shared__ __align__(16) float s_w[8448];
    __shared__ int s_off[512];

    int t = threadIdx.x;
    int p0 = blockIdx.x * 16;

    if (t < 45) s_kp[t] = kpts[t];
    __syncthreads();

    // phase 1: 512 (p,h) pairs over 2 iterations; warp-uniform p each iter
#pragma unroll
    for (int it = 0; it < 2; it++) {
        int id = t + it * 256;
        int p = id >> 5, h = id & 31;
        int idx = nbr[(p0 + p) * HN + h];
        bool valid = (unsigned)idx < NPTS;
        s_off[id] = valid ? idx * CMID : -1;
        float dx, dy, dz;
        if (valid) {
            dx = sp[idx * 3 + 0] - qp[(p0 + p) * 3 + 0];
            dy = sp[idx * 3 + 1] - qp[(p0 + p) * 3 + 1];
            dz = sp[idx * 3 + 2] - qp[(p0 + p) * 3 + 2];
        } else { dx = dy = dz = 1e10f; }
        unsigned m = __ballot_sync(0xffffffffu, valid);
        if ((t & 31) == 0) {
            int nn = __popc(m);
            g_nnr[p0 + p] = 1.0f / (float)(nn > 1 ? nn : 1);
        }
        float* wr = &s_w[(p * 32 + h) * 16 + p * 8];
#pragma unroll
        for (int k = 0; k < KP; k++) {
            float ex = dx - s_kp[k * 3 + 0];
            float ey = dy - s_kp[k * 3 + 1];
            float ez = dz - s_kp[k * 3 + 2];
            float dist = sqrtf(ex * ex + ey * ey + ez * ez);
            wr[k] = fmaxf(1.0f - dist, 0.0f);
        }
        wr[15] = 0.f;
    }
    __syncthreads();

    // phase 2: lane = (point-half, 4 channels)
    {
        int lane = t & 31;
        int pp = (t >> 5) * 2 + (lane >> 4);   // 0..15
        int c4 = (lane & 15) * 4;              // 0..60
        ull acc[8][4];
#pragma unroll
        for (int a = 0; a < 8; a++)
#pragma unroll
            for (int b = 0; b < 4; b++) acc[a][b] = 0ull;

        const int* offp = &s_off[pp * 32];
        const float* wbase = &s_w[pp * 32 * 16 + pp * 8];
#pragma unroll 4
        for (int h = 0; h < HN; h++) {
            int off = offp[h];
            float4 f = make_float4(0.f, 0.f, 0.f, 0.f);
            if (off >= 0) f = *(const float4*)&g_x1[(size_t)off + c4];
            ull fd0 = dup2(f.x), fd1 = dup2(f.y), fd2 = dup2(f.z), fd3 = dup2(f.w);
            const ulonglong2* w4 = (const ulonglong2*)&wbase[h * 16];
            ulonglong2 wa = w4[0], wb = w4[1], wcc = w4[2], wd = w4[3];
            fma2(acc[0][0], wa.x, fd0);  fma2(acc[0][1], wa.x, fd1);  fma2(acc[0][2], wa.x, fd2);  fma2(acc[0][3], wa.x, fd3);
            fma2(acc[1][0], wa.y, fd0);  fma2(acc[1][1], wa.y, fd1);  fma2(acc[1][2], wa.y, fd2);  fma2(acc[1][3], wa.y, fd3);
            fma2(acc[2][0], wb.x, fd0);  fma2(acc[2][1], wb.x, fd1);  fma2(acc[2][2], wb.x, fd2);  fma2(acc[2][3], wb.x, fd3);
            fma2(acc[3][0], wb.y, fd0);  fma2(acc[3][1], wb.y, fd1);  fma2(acc[3][2], wb.y, fd2);  fma2(acc[3][3], wb.y, fd3);
            fma2(acc[4][0], wcc.x, fd0); fma2(acc[4][1], wcc.x, fd1); fma2(acc[4][2], wcc.x, fd2); fma2(acc[4][3], wcc.x, fd3);
            fma2(acc[5][0], wcc.y, fd0); fma2(acc[5][1], wcc.y, fd1); fma2(acc[5][2], wcc.y, fd2); fma2(acc[5][3], wcc.y, fd3);
            fma2(acc[6][0], wd.x, fd0);  fma2(acc[6][1], wd.x, fd1);  fma2(acc[6][2], wd.x, fd2);  fma2(acc[6][3], wd.x, fd3);
            fma2(acc[7][0], wd.y, fd0);  fma2(acc[7][1], wd.y, fd1);  fma2(acc[7][2], wd.y, fd2);  fma2(acc[7][3], wd.y, fd3);
        }

        int n = p0 + pp;
        uint32_t* hiw = (uint32_t*)g_Ahi;
        uint32_t* low = (uint32_t*)g_Alo;
        int base = n * 480 + (c4 >> 1);
#pragma unroll
        for (int kp2 = 0; kp2 < 8; kp2++) {
            float2 v0 = up2(acc[kp2][0]);   // (k0, k0+1) for ch c4
            float2 v1 = up2(acc[kp2][1]);   // ch c4+1
            float2 v2 = up2(acc[kp2][2]);   // ch c4+2
            float2 v3 = up2(acc[kp2][3]);   // ch c4+3
            int k0 = kp2 * 2;
            {
                uint32_t h0, l0, h1, l1;
                split2(v0.x, v1.x, h0, l0);
                split2(v2.x, v3.x, h1, l1);
                *(uint2*)&hiw[base + k0 * 32] = make_uint2(h0, h1);
                *(uint2*)&low[base + k0 * 32] = make_uint2(l0, l1);
            }
            if (k0 + 1 < KP) {
                uint32_t h0, l0, h1, l1;
                split2(v0.y, v1.y, h0, l0);
                split2(v2.y, v3.y, h1, l1);
                *(uint2*)&hiw[base + (k0 + 1) * 32] = make_uint2(h0, h1);
                *(uint2*)&low[base + (k0 + 1) * 32] = make_uint2(l0, l1);
            }
        }
    }
}

// ---- k_pgemm: WMMA + cp.async double buffering + fused GN2 stats ----
#define PGS 72
#define PG_A(h, b) (sbp + (h) * 18432 + (b) * 9216)
#define PG_B(h, b) (sbp + 36864 + (h) * 9216 + (b) * 4608)
#define PG_SMEM (110592 + 512)

__global__ __launch_bounds__(256, 2) void k_pgemm(const float* __restrict__ kb) {
    extern __shared__ __nv_bfloat16 sbp[];
    float* s_stats = (float*)(sbp + 55296);
    float* sOut = (float*)sbp;

    int t = threadIdx.x;
    int warp = t >> 5;
    int wr = warp >> 1, wc = warp & 1;
    int row0 = blockIdx.x * 128;
    if (t < 128) s_stats[t] = 0.f;

    wmma::fragment<wmma::accumulator, 16, 16, 16, float> acc[2][2];
#pragma unroll
    for (int i = 0; i < 2; i++)
#pragma unroll
        for (int j = 0; j < 2; j++) wmma::fill_fragment(acc[i][j], 0.0f);

    const __nv_bfloat16* Ahi = g_Ahi + (size_t)row0 * 960;
    const __nv_bfloat16* Alo = g_Alo + (size_t)row0 * 960;

    auto fill = [&](int ch, int b) {
#pragma unroll
        for (int i = 0; i < 4; i++) {
            int e = t + i * 256;
            int r = e >> 3, j = e & 7;
            cp16(PG_A(0, b) + r * PGS + j * 8, Ahi + (size_t)r * 960 + ch * 64 + j * 8);
            cp16(PG_A(1, b) + r * PGS + j * 8, Alo + (size_t)r * 960 + ch * 64 + j * 8);
        }
#pragma unroll
        for (int i = 0; i < 2; i++) {
            int e = t + i * 256;
            int r = e >> 3, j = e & 7;
            cp16(PG_B(0, b) + r * PGS + j * 8, g_BhiT + (size_t)r * 960 + ch * 64 + j * 8);
            cp16(PG_B(1, b) + r * PGS + j * 8, g_BloT + (size_t)r * 960 + ch * 64 + j * 8);
        }
    };

    fill(0, 0);
    CP_COMMIT();

    for (int ch = 0; ch < 15; ch++) {
        int buf = ch & 1;
        if (ch < 14) {
            fill(ch + 1, buf ^ 1);
            CP_COMMIT();
            CP_WAIT(1);
        } else {
            CP_WAIT(0);
        }
        __syncthreads();

        __nv_bfloat16* sAhi = PG_A(0, buf);
        __nv_bfloat16* sAlo = PG_A(1, buf);
        __nv_bfloat16* sBhi = PG_B(0, buf);
        __nv_bfloat16* sBlo = PG_B(1, buf);
#pragma unroll
        for (int kk = 0; kk < 4; kk++) {
            wmma::fragment<wmma::matrix_a, 16, 16, 16, __nv_bfloat16, wmma::row_major> a_hi[2], a_lo[2];
            wmma::fragment<wmma::matrix_b, 16, 16, 16, __nv_bfloat16, wmma::col_major> b_hi[2], b_lo[2];
#pragma unroll
            for (int i = 0; i < 2; i++) {
                wmma::load_matrix_sync(a_hi[i], &sAhi[(wr * 32 + i * 16) * PGS + kk * 16], PGS);
                wmma::load_matrix_sync(a_lo[i], &sAlo[(wr * 32 + i * 16) * PGS + kk * 16], PGS);
            }
#pragma unroll
            for (int j = 0; j < 2; j++) {
                wmma::load_matrix_sync(b_hi[j], &sBhi[(wc * 32 + j * 16) * PGS + kk * 16], PGS);
                wmma::load_matrix_sync(b_lo[j], &sBlo[(wc * 32 + j * 16) * PGS + kk * 16], PGS);
            }
#pragma unroll
            for (int i = 0; i < 2; i++)
#pragma unroll
                for (int j = 0; j < 2; j++) {
                    wmma::mma_sync(acc[i][j], a_hi[i], b_hi[j], acc[i][j]);
                    wmma::mma_sync(acc[i][j], a_lo[i], b_hi[j], acc[i][j]);
                    wmma::mma_sync(acc[i][j], a_hi[i], b_lo[j], acc[i][j]);
                }
        }
        __syncthreads();
    }

#pragma unroll
    for (int i = 0; i < 2; i++)
#pragma unroll
        for (int j = 0; j < 2; j++)
            wmma::store_matrix_sync(&sOut[(wr * 32 + i * 16) * PGS + wc * 32 + j * 16],
                                    acc[i][j], PGS, wmma::mem_row_major);
    __syncthreads();

    {
        int c4 = t & 15;
        float b0 = kb[c4 * 4 + 0], b1 = kb[c4 * 4 + 1];
        float b2 = kb[c4 * 4 + 2], b3 = kb[c4 * 4 + 3];
        float cs[4] = {0, 0, 0, 0}, cq[4] = {0, 0, 0, 0};
#pragma unroll
        for (int i = 0; i < 8; i++) {
            int r = (t >> 4) + i * 16;
            float nnr = g_nnr[row0 + r];
            float4 v = *(const float4*)&sOut[r * PGS + c4 * 4];
            v.x = v.x * nnr + b0;
            v.y = v.y * nnr + b1;
            v.z = v.z * nnr + b2;
            v.w = v.w * nnr + b3;
            *(float4*)&g_out2[(size_t)(row0 + r) * CMID + c4 * 4] = v;
            cs[0] += v.x; cq[0] += v.x * v.x;
            cs[1] += v.y; cq[1] += v.y * v.y;
            cs[2] += v.z; cq[2] += v.z * v.z;
            cs[3] += v.w; cq[3] += v.w * v.w;
        }
#pragma unroll
        for (int j = 0; j < 4; j++) {
            atomicAdd(&s_stats[c4 * 4 + j], cs[j]);
            atomicAdd(&s_stats[64 + c4 * 4 + j], cq[j]);
        }
    }
    __syncthreads();
    if (t < 64) {
        atomicAdd(&g_sum2[t], (double)s_stats[t]);
        atomicAdd(&g_sq2[t], (double)s_stats[64 + t]);
    }
}

// ---- GEMM2 (WMMA bf16 hi/lo): y = leaky(GN2(out2)) @ W2 + b2 ; GN3 stats ----
#define G2AS 72
#define G2BS 264
#define G2_SMEM (86016 + 2048 + 512)

__global__ __launch_bounds__(256) void k_gemm2(const float* __restrict__ W2,
                                               const float* __restrict__ b2,
                                               const float* __restrict__ gg,
                                               const float* __restrict__ gb) {
    extern __shared__ __nv_bfloat16 sb2[];
    __nv_bfloat16* sAhi = sb2;
    __nv_bfloat16* sAlo = sb2 + 4608;
    __nv_bfloat16* sBhi = sb2 + 9216;
    __nv_bfloat16* sBlo = sb2 + 26112;
    float* s_stats = (float*)((char*)sb2 + 86016);
    float* s_a2 = (float*)((char*)sb2 + 86016 + 2048);
    float* s_b2 = s_a2 + 64;
    float* sOut = (float*)sb2;

    int t = threadIdx.x;
    int warp = t >> 5;
    int wr = warp >> 2, wc = warp & 3;
    int row0 = blockIdx.x * 64;
    s_stats[t] = 0.f; s_stats[t + 256] = 0.f;
    if (t < 64) {
        int g = t >> 1;
        double s = g_sum2[g * 2] + g_sum2[g * 2 + 1];
        double q = g_sq2[g * 2] + g_sq2[g * 2 + 1];
        double cnt = 2.0 * (double)NPTS;
        double mean = s / cnt;
        double var = q / cnt - mean * mean;
        float inv = rsqrtf((float)var + EPSV);
        float av = gg[t] * inv;
        s_a2[t] = av;
        s_b2[t] = gb[t] - (float)mean * av;
    }
    __syncthreads();

#pragma unroll
    for (int i = 0; i < 4; i++) {
        int e = t + i * 256;
        int r = e >> 4, j = e & 15;
        float4 v = *(const float4*)&g_out2[(size_t)(row0 + r) * CMID + j * 4];
        float a0 = s_a2[j * 4 + 0], a1 = s_a2[j * 4 + 1], a2 = s_a2[j * 4 + 2], a3 = s_a2[j * 4 + 3];
        float c0 = s_b2[j * 4 + 0], c1 = s_b2[j * 4 + 1], c2 = s_b2[j * 4 + 2], c3 = s_b2[j * 4 + 3];
        v.x = a0 * v.x + c0; v.x = v.x >= 0.f ? v.x : SLOPE * v.x;
        v.y = a1 * v.y + c1; v.y = v.y >= 0.f ? v.y : SLOPE * v.y;
        v.z = a2 * v.z + c2; v.z = v.z >= 0.f ? v.z : SLOPE * v.z;
        v.w = a3 * v.w + c3; v.w = v.w >= 0.f ? v.w : SLOPE * v.w;
        uint32_t h0, l0, h1, l1;
        split2(v.x, v.y, h0, l0);
        split2(v.z, v.w, h1, l1);
        *(uint2*)&sAhi[r * G2AS + j * 4] = make_uint2(h0, h1);
        *(uint2*)&sAlo[r * G2AS + j * 4] = make_uint2(l0, l1);
    }
#pragma unroll
    for (int i = 0; i < 16; i++) {
        int e = t + i * 256;
        int r = e >> 6, j = e & 63;
        float4 v = *(const float4*)&W2[(size_t)r * COUT + j * 4];
        uint32_t h0, l0, h1, l1;
        split2(v.x, v.y, h0, l0);
        split2(v.z, v.w, h1, l1);
        *(uint2*)&sBhi[r * G2BS + j * 4] = make_uint2(h0, h1);
        *(uint2*)&sBlo[r * G2BS + j * 4] = make_uint2(l0, l1);
    }
    __syncthreads();

    wmma::fragment<wmma::accumulator, 16, 16, 16, float> acc[2][4];
#pragma unroll
    for (int i = 0; i < 2; i++)
#pragma unroll
        for (int j = 0; j < 4; j++) wmma::fill_fragment(acc[i][j], 0.0f);

#pragma unroll
    for (int kk = 0; kk < 4; kk++) {
        wmma::fragment<wmma::matrix_a, 16, 16, 16, __nv_bfloat16, wmma::row_major> a_hi[2], a_lo[2];
        wmma::fragment<wmma::matrix_b, 16, 16, 16, __nv_bfloat16, wmma::row_major> b_hi[4], b_lo[4];
#pragma unroll
        for (int i = 0; i < 2; i++) {
            wmma::load_matrix_sync(a_hi[i], &sAhi[(wr * 32 + i * 16) * G2AS + kk * 16], G2AS);
            wmma::load_matrix_sync(a_lo[i], &sAlo[(wr * 32 + i * 16) * G2AS + kk * 16], G2AS);
        }
#pragma unroll
        for (int j = 0; j < 4; j++) {
            wmma::load_matrix_sync(b_hi[j], &sBhi[(kk * 16) * G2BS + wc * 64 + j * 16], G2BS);
            wmma::load_matrix_sync(b_lo[j], &sBlo[(kk * 16) * G2BS + wc * 64 + j * 16], G2BS);
        }
#pragma unroll
        for (int i = 0; i < 2; i++)
#pragma unroll
            for (int j = 0; j < 4; j++) {
                wmma::mma_sync(acc[i][j], a_hi[i], b_hi[j], acc[i][j]);
                wmma::mma_sync(acc[i][j], a_lo[i], b_hi[j], acc[i][j]);
                wmma::mma_sync(acc[i][j], a_hi[i], b_lo[j], acc[i][j]);
            }
    }

    __syncthreads();
#pragma unroll
    for (int i = 0; i < 2; i++)
#pragma unroll
        for (int j = 0; j < 4; j++)
            wmma::store_matrix_sync(&sOut[(wr * 32 + i * 16) * G2BS + wc * 64 + j * 16],
                                    acc[i][j], G2BS, wmma::mem_row_major);
    __syncthreads();

    {
        int c4 = t & 63;
        float b0 = b2[c4 * 4 + 0], b1 = b2[c4 * 4 + 1];
        float bb2 = b2[c4 * 4 + 2], b3 = b2[c4 * 4 + 3];
        float cs[4] = {0, 0, 0, 0}, cq[4] = {0, 0, 0, 0};
#pragma unroll
        for (int i = 0; i < 16; i++) {
            int r = (t >> 6) + i * 4;
            float4 v = *(const float4*)&sOut[r * G2BS + c4 * 4];
            v.x += b0; v.y += b1; v.z += bb2; v.w += b3;
            *(float4*)&g_y[(size_t)(row0 + r) * COUT + c4 * 4] = v;
            cs[0] += v.x; cq[0] += v.x * v.x;
            cs[1] += v.y; cq[1] += v.y * v.y;
            cs[2] += v.z; cq[2] += v.z * v.z;
            cs[3] += v.w; cq[3] += v.w * v.w;
        }
#pragma unroll
        for (int j = 0; j < 4; j++) {
            atomicAdd(&s_stats[c4 * 4 + j], cs[j]);
            atomicAdd(&s_stats[256 + c4 * 4 + j], cq[j]);
        }
    }
    __syncthreads();
    atomicAdd(&g_sum3[t], (double)s_stats[t]);
    atomicAdd(&g_sq3[t], (double)s_stats[256 + t]);
}

// ---- final: out = leaky(GN3(y) + s_feats), inline GN3 finalize, MLP-8 ----
__global__ __launch_bounds__(256) void k_final(const float* __restrict__ sf,
                                               const float* __restrict__ g2f,
                                               const float* __restrict__ beta2f,
                                               float* __restrict__ out) {
    __shared__ float s_a[256], s_b[256];
    int t = threadIdx.x;
    {
        int g = t >> 3;
        double s = 0.0, q = 0.0;
#pragma unroll
        for (int i = 0; i < 8; i++) { s += g_sum3[g * 8 + i]; q += g_sq3[g * 8 + i]; }
        double cnt = 8.0 * (double)NPTS;
        double mean = s / cnt;
        double var = q / cnt - mean * mean;
        float inv = rsqrtf((float)var + EPSV);
        float av = g2f[t] * inv;
        s_a[t] = av;
        s_b[t] = beta2f[t] - (float)mean * av;
    }
    __syncthreads();
    int base = blockIdx.x * 1024 + t;
    int c = (base & 63) * 4;
    float a0 = s_a[c + 0], a1 = s_a[c + 1], a2 = s_a[c + 2], a3 = s_a[c + 3];
    float b0 = s_b[c + 0], b1 = s_b[c + 1], b2 = s_b[c + 2], b3 = s_b[c + 3];
    float4 y[4], s[4];
#pragma unroll
    for (int u = 0; u < 4; u++) {
        y[u] = ((const float4*)g_y)[base + u * 256];
        s[u] = ((const float4*)sf)[base + u * 256];
    }
#pragma unroll
    for (int u = 0; u < 4; u++) {
        float4 r;
        r.x = a0 * y[u].x + b0 + s[u].x;
        r.y = a1 * y[u].y + b1 + s[u].y;
        r.z = a2 * y[u].z + b2 + s[u].z;
        r.w = a3 * y[u].w + b3 + s[u].w;
        r.x = r.x >= 0.f ? r.x : SLOPE * r.x;
        r.y = r.y >= 0.f ? r.y : SLOPE * r.y;
        r.z = r.z >= 0.f ? r.z : SLOPE * r.z;
        r.w = r.w >= 0.f ? r.w : SLOPE * r.w;
        ((float4*)out)[base + u * 256] = r;
    }
}

extern "C" void kernel_launch(void* const* d_in, const int* in_sizes, int n_in,
                              void* d_out, int out_size) {
    const float* s_feats  = (const float*)d_in[0];
    const float* q_points = (const float*)d_in[1];
    const float* s_points = (const float*)d_in[2];
    const int*   nbr      = (const int*)d_in[3];
    const float* W1       = (const float*)d_in[4];
    const float* b1       = (const float*)d_in[5];
    const float* g1       = (const float*)d_in[6];
    const float* beta1    = (const float*)d_in[7];
    const float* kpw      = (const float*)d_in[8];
    const float* kpb      = (const float*)d_in[9];
    const float* kpts     = (const float*)d_in[10];
    const float* gg       = (const float*)d_in[11];
    const float* gb       = (const float*)d_in[12];
    const float* W2       = (const float*)d_in[13];
    const float* b2       = (const float*)d_in[14];
    const float* g2       = (const float*)d_in[15];
    const float* beta2    = (const float*)d_in[16];
    float* out = (float*)d_out;

    cudaFuncSetAttribute(k_gemm1, cudaFuncAttributeMaxDynamicSharedMemorySize, G1_SMEM);
    cudaFuncSetAttribute(k_pgemm, cudaFuncAttributeMaxDynamicSharedMemorySize, PG_SMEM);
    cudaFuncSetAttribute(k_gemm2, cudaFuncAttributeMaxDynamicSharedMemorySize, G2_SMEM);

    k_prep<<<240, 256>>>(kpw);
    k_gemm1<<<NPTS / 128, 256, G1_SMEM>>>(s_feats, W1, b1);
    k_apply1<<<NPTS * CMID / 4 / 1024, 256>>>(g1, beta1);
    k_gather<<<NPTS / 16, 256>>>(q_points, s_points, nbr, kpts);
    k_pgemm<<<NPTS / 128, 256, PG_SMEM>>>(kpb);
    k_gemm2<<<NPTS / 64, 256, G2_SMEM>>>(W2, b2, gg, gb);
    k_final<<<NPTS * COUT / 4 / 1024, 256>>>(s_feats, g2, beta2, out);
}

// round 15
// speedup vs baseline: 1.0163x; 1.0163x over previous
#include <cuda_runtime.h>
#include <cuda_bf16.h>
#include <mma.h>
#include <cstdint>

#define NPTS 65536
#define HN 32
#define CIN 256
#define CMID 64
#define COUT 256
#define KP 15
#define SLOPE 0.1f
#define EPSV 1e-5f

using ull = unsigned long long;
using namespace nvcuda;

// ---- packed f32x2 helpers ----
__device__ __forceinline__ ull pk2(float lo, float hi) {
    ull r; asm("mov.b64 %0, {%1,%2};" : "=l"(r) : "f"(lo), "f"(hi)); return r;
}
__device__ __forceinline__ ull dup2(float v) { return pk2(v, v); }
__device__ __forceinline__ void fma2(ull& d, ull a, ull b) {
    asm("fma.rn.f32x2 %0, %1, %2, %3;" : "=l"(d) : "l"(a), "l"(b), "l"(d));
}
__device__ __forceinline__ float2 up2(ull v) {
    float lo, hi; asm("mov.b64 {%0,%1}, %2;" : "=f"(lo), "=f"(hi) : "l"(v));
    return make_float2(lo, hi);
}

// ---- cp.async helpers ----
__device__ __forceinline__ void cp16(void* sdst, const void* gsrc) {
    uint32_t s = (uint32_t)__cvta_generic_to_shared(sdst);
    asm volatile("cp.async.cg.shared.global [%0], [%1], 16;" :: "r"(s), "l"(gsrc));
}
#define CP_COMMIT() asm volatile("cp.async.commit_group;" ::: "memory")
#define CP_WAIT(n)  asm volatile("cp.async.wait_group %0;" :: "n"(n) : "memory")

// ---- hi/lo split helper ----
__device__ __forceinline__ void split2(float x, float y, uint32_t& h, uint32_t& l) {
    __nv_bfloat162 hh = __floats2bfloat162_rn(x, y);
    __nv_bfloat162 ll = __floats2bfloat162_rn(x - __bfloat162float(hh.x),
                                              y - __bfloat162float(hh.y));
    h = *(uint32_t*)&hh;
    l = *(uint32_t*)&ll;
}

// ---- scratch (device globals; aligned for vector-cast access) ----
__device__ __align__(256) float g_x1[NPTS * CMID];            // 16 MB
__device__ __align__(256) float g_out2[NPTS * CMID];          // 16 MB
__device__ __align__(256) float g_y[NPTS * COUT];             // 64 MB
__device__ __align__(256) __nv_bfloat16 g_Ahi[NPTS * 960];    // 126 MB
__device__ __align__(256) __nv_bfloat16 g_Alo[NPTS * 960];    // 126 MB
__device__ __align__(256) __nv_bfloat16 g_BhiT[64 * 960];
__device__ __align__(256) __nv_bfloat16 g_BloT[64 * 960];
__device__ float g_nnr[NPTS];
__device__ double g_sum1[CMID], g_sq1[CMID];
__device__ double g_sum2[CMID], g_sq2[CMID];
__device__ double g_sum3[COUT], g_sq3[COUT];

// ---- k_prep: zero stats (block 0) + kw transpose/split ----
__global__ __launch_bounds__(256) void k_prep(const float* __restrict__ kw) {
    int t = threadIdx.x;
    if (blockIdx.x == 0) {
        if (t < CMID) { g_sum1[t] = 0.0; g_sq1[t] = 0.0; g_sum2[t] = 0.0; g_sq2[t] = 0.0; }
        if (t < COUT) { g_sum3[t] = 0.0; g_sq3[t] = 0.0; }
    }
    int idx = blockIdx.x * 256 + t;
    int d = idx / 960;
    int r = idx % 960;
    float v = kw[r * 64 + d];
    __nv_bfloat16 h = __float2bfloat16(v);
    g_BhiT[d * 960 + r] = h;
    g_BloT[d * 960 + r] = __float2bfloat16(v - __bfloat162float(h));
}

// ---- GEMM1 (WMMA bf16 hi/lo): x1 = s_feats @ W1 + b1 ; GN1 stats ----
#define G1S 72
#define G1_SMEM (55296 + 512)

__global__ __launch_bounds__(256) void k_gemm1(const float* __restrict__ A,
                                               const float* __restrict__ W,
                                               const float* __restrict__ bias) {
    extern __shared__ __nv_bfloat16 sb1[];
    __nv_bfloat16* sAhi = sb1;
    __nv_bfloat16* sAlo = sb1 + 9216;
    __nv_bfloat16* sBhi = sb1 + 18432;
    __nv_bfloat16* sBlo = sb1 + 23040;
    float* s_stats = (float*)(sb1 + 27648);
    float* sOut = (float*)sb1;

    int t = threadIdx.x;
    int warp = t >> 5;
    int wr = warp >> 1, wc = warp & 1;
    int row0 = blockIdx.x * 128;
    if (t < 128) s_stats[t] = 0.f;

    wmma::fragment<wmma::accumulator, 16, 16, 16, float> acc[2][2];
#pragma unroll
    for (int i = 0; i < 2; i++)
#pragma unroll
        for (int j = 0; j < 2; j++) wmma::fill_fragment(acc[i][j], 0.0f);

    for (int ch = 0; ch < 4; ch++) {
        __syncthreads();
#pragma unroll
        for (int i = 0; i < 8; i++) {
            int e = t + i * 256;
            int r = e >> 4, j = e & 15;
            float4 v = *(const float4*)&A[(size_t)(row0 + r) * CIN + ch * 64 + j * 4];
            uint32_t h0, l0, h1, l1;
            split2(v.x, v.y, h0, l0);
            split2(v.z, v.w, h1, l1);
            *(uint2*)&sAhi[r * G1S + j * 4] = make_uint2(h0, h1);
            *(uint2*)&sAlo[r * G1S + j * 4] = make_uint2(l0, l1);
        }
#pragma unroll
        for (int i = 0; i < 4; i++) {
            int e = t + i * 256;
            int r = e >> 4, j = e & 15;
            float4 v = *(const float4*)&W[(size_t)(ch * 64 + r) * CMID + j * 4];
            uint32_t h0, l0, h1, l1;
            split2(v.x, v.y, h0, l0);
            split2(v.z, v.w, h1, l1);
            *(uint2*)&sBhi[r * G1S + j * 4] = make_uint2(h0, h1);
            *(uint2*)&sBlo[r * G1S + j * 4] = make_uint2(l0, l1);
        }
        __syncthreads();

#pragma unroll
        for (int kk = 0; kk < 4; kk++) {
            wmma::fragment<wmma::matrix_a, 16, 16, 16, __nv_bfloat16, wmma::row_major> a_hi[2], a_lo[2];
            wmma::fragment<wmma::matrix_b, 16, 16, 16, __nv_bfloat16, wmma::row_major> b_hi[2], b_lo[2];
#pragma unroll
            for (int i = 0; i < 2; i++) {
                wmma::load_matrix_sync(a_hi[i], &sAhi[(wr * 32 + i * 16) * G1S + kk * 16], G1S);
                wmma::load_matrix_sync(a_lo[i], &sAlo[(wr * 32 + i * 16) * G1S + kk * 16], G1S);
            }
#pragma unroll
            for (int j = 0; j < 2; j++) {
                wmma::load_matrix_sync(b_hi[j], &sBhi[(kk * 16) * G1S + wc * 32 + j * 16], G1S);
                wmma::load_matrix_sync(b_lo[j], &sBlo[(kk * 16) * G1S + wc * 32 + j * 16], G1S);
            }
#pragma unroll
            for (int i = 0; i < 2; i++)
#pragma unroll
                for (int j = 0; j < 2; j++) {
                    wmma::mma_sync(acc[i][j], a_hi[i], b_hi[j], acc[i][j]);
                    wmma::mma_sync(acc[i][j], a_lo[i], b_hi[j], acc[i][j]);
                    wmma::mma_sync(acc[i][j], a_hi[i], b_lo[j], acc[i][j]);
                }
        }
    }

    __syncthreads();
#pragma unroll
    for (int i = 0; i < 2; i++)
#pragma unroll
        for (int j = 0; j < 2; j++)
            wmma::store_matrix_sync(&sOut[(wr * 32 + i * 16) * G1S + wc * 32 + j * 16],
                                    acc[i][j], G1S, wmma::mem_row_major);
    __syncthreads();

    {
        int c4 = t & 15;
        float b0 = bias[c4 * 4 + 0], b1 = bias[c4 * 4 + 1];
        float b2 = bias[c4 * 4 + 2], b3 = bias[c4 * 4 + 3];
        float cs[4] = {0, 0, 0, 0}, cq[4] = {0, 0, 0, 0};
#pragma unroll
        for (int i = 0; i < 8; i++) {
            int r = (t >> 4) + i * 16;
            float4 v = *(const float4*)&sOut[r * G1S + c4 * 4];
            v.x += b0; v.y += b1; v.z += b2; v.w += b3;
            *(float4*)&g_x1[(size_t)(row0 + r) * CMID + c4 * 4] = v;
            cs[0] += v.x; cq[0] += v.x * v.x;
            cs[1] += v.y; cq[1] += v.y * v.y;
            cs[2] += v.z; cq[2] += v.z * v.z;
            cs[3] += v.w; cq[3] += v.w * v.w;
        }
#pragma unroll
        for (int j = 0; j < 4; j++) {
            atomicAdd(&s_stats[c4 * 4 + j], cs[j]);
            atomicAdd(&s_stats[64 + c4 * 4 + j], cq[j]);
        }
    }
    __syncthreads();
    if (t < 64) {
        atomicAdd(&g_sum1[t], (double)s_stats[t]);
        atomicAdd(&g_sq1[t], (double)s_stats[64 + t]);
    }
}

// ---- k_apply1: GN1 + leaky in place on x1 (inline stat finalize, MLP-4) ----
__global__ __launch_bounds__(256) void k_apply1(const float* __restrict__ gamma,
                                                const float* __restrict__ beta) {
    __shared__ float s_a[64], s_b[64];
    int t = threadIdx.x;
    if (t < 64) {
        int g = t >> 1;
        double s = g_sum1[g * 2] + g_sum1[g * 2 + 1];
        double q = g_sq1[g * 2] + g_sq1[g * 2 + 1];
        double cnt = 2.0 * (double)NPTS;
        double mean = s / cnt;
        double var = q / cnt - mean * mean;
        float inv = rsqrtf((float)var + EPSV);
        float av = gamma[t] * inv;
        s_a[t] = av;
        s_b[t] = beta[t] - (float)mean * av;
    }
    __syncthreads();
    int base = blockIdx.x * 1024 + t;
    int c = (base & 15) * 4;
    float a0 = s_a[c + 0], a1 = s_a[c + 1], a2 = s_a[c + 2], a3 = s_a[c + 3];
    float b0 = s_b[c + 0], b1 = s_b[c + 1], b2 = s_b[c + 2], b3 = s_b[c + 3];
    float4 v[4];
#pragma unroll
    for (int u = 0; u < 4; u++) v[u] = ((const float4*)g_x1)[base + u * 256];
#pragma unroll
    for (int u = 0; u < 4; u++) {
        float4 r;
        r.x = a0 * v[u].x + b0;
        r.y = a1 * v[u].y + b1;
        r.z = a2 * v[u].z + b2;
        r.w = a3 * v[u].w + b3;
        r.x = r.x >= 0.f ? r.x : SLOPE * r.x;
        r.y = r.y >= 0.f ? r.y : SLOPE * r.y;
        r.z = r.z >= 0.f ? r.z : SLOPE * r.z;
        r.w = r.w >= 0.f ? r.w : SLOPE * r.w;
        ((float4*)g_x1)[base + u * 256] = r;
    }
}

// ---- k_gather: 8 pts/block, 1 pt/warp, 2 ch/lane; stride-20 s_w, STS.128 writes ----
#define WST 20
__global__ __launch_bounds__(256, 3) void k_gather(
        const float* __restrict__ qp, const float* __restrict__ sp,
        const int* __restrict__ nbr, const float* __restrict__ kpts) {
    __shared__ float s_kp[48];
    __shared__ __align__(16) float s_w[8 * 32 * WST];   // 20 KB
    __shared__ int s_off[256];

    int t = threadIdx.x;
    int p0 = blockIdx.x * 8;

    if (t < 45) s_kp[t] = kpts[t];
    __syncthreads();

    // phase 1: lane = h for point p (warp-uniform); vectorized conflict-light writes
    {
        int p = t >> 5, h = t & 31;
        int idx = nbr[(p0 + p) * HN + h];
        bool valid = (unsigned)idx < NPTS;
        s_off[t] = valid ? idx * CMID : -1;
        float dx, dy, dz;
        if (valid) {
            dx = sp[idx * 3 + 0] - qp[(p0 + p) * 3 + 0];
            dy = sp[idx * 3 + 1] - qp[(p0 + p) * 3 + 1];
            dz = sp[idx * 3 + 2] - qp[(p0 + p) * 3 + 2];
        } else { dx = dy = dz = 1e10f; }
        unsigned m = __ballot_sync(0xffffffffu, valid);
        if ((t & 31) == 0) {
            int nn = __popc(m);
            g_nnr[p0 + p] = 1.0f / (float)(nn > 1 ? nn : 1);
        }
        float w[16];
#pragma unroll
        for (int k = 0; k < KP; k++) {
            float ex = dx - s_kp[k * 3 + 0];
            float ey = dy - s_kp[k * 3 + 1];
            float ez = dz - s_kp[k * 3 + 2];
            float dist = sqrtf(ex * ex + ey * ey + ez * ez);
            w[k] = fmaxf(1.0f - dist, 0.0f);
        }
        w[15] = 0.f;
        float4* wr = (float4*)&s_w[t * WST];
        wr[0] = make_float4(w[0], w[1], w[2], w[3]);
        wr[1] = make_float4(w[4], w[5], w[6], w[7]);
        wr[2] = make_float4(w[8], w[9], w[10], w[11]);
        wr[3] = make_float4(w[12], w[13], w[14], w[15]);
    }
    __syncthreads();

    // phase 2: thread = (p, 2 channels); weights via 4x broadcast LDS.128
    {
        int p = t >> 5;
        int c2 = (t & 31) * 2;
        ull acc[8][2];
#pragma unroll
        for (int a = 0; a < 8; a++) { acc[a][0] = 0ull; acc[a][1] = 0ull; }
        const int* offp = &s_off[p * 32];
#pragma unroll 4
        for (int h = 0; h < HN; h++) {
            int off = offp[h];
            float2 f = make_float2(0.f, 0.f);
            if (off >= 0) f = *(const float2*)&g_x1[(size_t)off + c2];
            ull fd0 = dup2(f.x), fd1 = dup2(f.y);
            const ulonglong2* w4 = (const ulonglong2*)&s_w[(p * 32 + h) * WST];
            ulonglong2 wa = w4[0], wb = w4[1], wcc = w4[2], wd = w4[3];
            fma2(acc[0][0], wa.x, fd0);  fma2(acc[0][1], wa.x, fd1);
            fma2(acc[1][0], wa.y, fd0);  fma2(acc[1][1], wa.y, fd1);
            fma2(acc[2][0], wb.x, fd0);  fma2(acc[2][1], wb.x, fd1);
            fma2(acc[3][0], wb.y, fd0);  fma2(acc[3][1], wb.y, fd1);
            fma2(acc[4][0], wcc.x, fd0); fma2(acc[4][1], wcc.x, fd1);
            fma2(acc[5][0], wcc.y, fd0); fma2(acc[5][1], wcc.y, fd1);
            fma2(acc[6][0], wd.x, fd0);  fma2(acc[6][1], wd.x, fd1);
            fma2(acc[7][0], wd.y, fd0);  fma2(acc[7][1], wd.y, fd1);
        }
        int n = p0 + p;
        uint32_t* hiw = (uint32_t*)g_Ahi;
        uint32_t* low = (uint32_t*)g_Alo;
        int base = n * 480 + (c2 >> 1);
#pragma unroll
        for (int kp2 = 0; kp2 < 8; kp2++) {
            float2 a0 = up2(acc[kp2][0]);
            float2 a1 = up2(acc[kp2][1]);
            int k0 = kp2 * 2;
            {
                uint32_t h, l;
                split2(a0.x, a1.x, h, l);
                hiw[base + k0 * 32] = h;
                low[base + k0 * 32] = l;
            }
            if (k0 + 1 < KP) {
                uint32_t h, l;
                split2(a0.y, a1.y, h, l);
                hiw[base + (k0 + 1) * 32] = h;
                low[base + (k0 + 1) * 32] = l;
            }
        }
    }
}

// ---- k_pgemm: WMMA + cp.async double buffering + fused GN2 stats ----
#define PGS 72
#define PG_A(h, b) (sbp + (h) * 18432 + (b) * 9216)
#define PG_B(h, b) (sbp + 36864 + (h) * 9216 + (b) * 4608)
#define PG_SMEM (110592 + 512)

__global__ __launch_bounds__(256, 2) void k_pgemm(const float* __restrict__ kb) {
    extern __shared__ __nv_bfloat16 sbp[];
    float* s_stats = (float*)(sbp + 55296);
    float* sOut = (float*)sbp;

    int t = threadIdx.x;
    int warp = t >> 5;
    int wr = warp >> 1, wc = warp & 1;
    int row0 = blockIdx.x * 128;
    if (t < 128) s_stats[t] = 0.f;

    wmma::fragment<wmma::accumulator, 16, 16, 16, float> acc[2][2];
#pragma unroll
    for (int i = 0; i < 2; i++)
#pragma unroll
        for (int j = 0; j < 2; j++) wmma::fill_fragment(acc[i][j], 0.0f);

    const __nv_bfloat16* Ahi = g_Ahi + (size_t)row0 * 960;
    const __nv_bfloat16* Alo = g_Alo + (size_t)row0 * 960;

    auto fill = [&](int ch, int b) {
#pragma unroll
        for (int i = 0; i < 4; i++) {
            int e = t + i * 256;
            int r = e >> 3, j = e & 7;
            cp16(PG_A(0, b) + r * PGS + j * 8, Ahi + (size_t)r * 960 + ch * 64 + j * 8);
            cp16(PG_A(1, b) + r * PGS + j * 8, Alo + (size_t)r * 960 + ch * 64 + j * 8);
        }
#pragma unroll
        for (int i = 0; i < 2; i++) {
            int e = t + i * 256;
            int r = e >> 3, j = e & 7;
            cp16(PG_B(0, b) + r * PGS + j * 8, g_BhiT + (size_t)r * 960 + ch * 64 + j * 8);
            cp16(PG_B(1, b) + r * PGS + j * 8, g_BloT + (size_t)r * 960 + ch * 64 + j * 8);
        }
    };

    fill(0, 0);
    CP_COMMIT();

    for (int ch = 0; ch < 15; ch++) {
        int buf = ch & 1;
        if (ch < 14) {
            fill(ch + 1, buf ^ 1);
            CP_COMMIT();
            CP_WAIT(1);
        } else {
            CP_WAIT(0);
        }
        __syncthreads();

        __nv_bfloat16* sAhi = PG_A(0, buf);
        __nv_bfloat16* sAlo = PG_A(1, buf);
        __nv_bfloat16* sBhi = PG_B(0, buf);
        __nv_bfloat16* sBlo = PG_B(1, buf);
#pragma unroll
        for (int kk = 0; kk < 4; kk++) {
            wmma::fragment<wmma::matrix_a, 16, 16, 16, __nv_bfloat16, wmma::row_major> a_hi[2], a_lo[2];
            wmma::fragment<wmma::matrix_b, 16, 16, 16, __nv_bfloat16, wmma::col_major> b_hi[2], b_lo[2];
#pragma unroll
            for (int i = 0; i < 2; i++) {
                wmma::load_matrix_sync(a_hi[i], &sAhi[(wr * 32 + i * 16) * PGS + kk * 16], PGS);
                wmma::load_matrix_sync(a_lo[i], &sAlo[(wr * 32 + i * 16) * PGS + kk * 16], PGS);
            }
#pragma unroll
            for (int j = 0; j < 2; j++) {
                wmma::load_matrix_sync(b_hi[j], &sBhi[(wc * 32 + j * 16) * PGS + kk * 16], PGS);
                wmma::load_matrix_sync(b_lo[j], &sBlo[(wc * 32 + j * 16) * PGS + kk * 16], PGS);
            }
#pragma unroll
            for (int i = 0; i < 2; i++)
#pragma unroll
                for (int j = 0; j < 2; j++) {
                    wmma::mma_sync(acc[i][j], a_hi[i], b_hi[j], acc[i][j]);
                    wmma::mma_sync(acc[i][j], a_lo[i], b_hi[j], acc[i][j]);
                    wmma::mma_sync(acc[i][j], a_hi[i], b_lo[j], acc[i][j]);
                }
        }
        __syncthreads();
    }

#pragma unroll
    for (int i = 0; i < 2; i++)
#pragma unroll
        for (int j = 0; j < 2; j++)
            wmma::store_matrix_sync(&sOut[(wr * 32 + i * 16) * PGS + wc * 32 + j * 16],
                                    acc[i][j], PGS, wmma::mem_row_major);
    __syncthreads();

    {
        int c4 = t & 15;
        float b0 = kb[c4 * 4 + 0], b1 = kb[c4 * 4 + 1];
        float b2 = kb[c4 * 4 + 2], b3 = kb[c4 * 4 + 3];
        float cs[4] = {0, 0, 0, 0}, cq[4] = {0, 0, 0, 0};
#pragma unroll
        for (int i = 0; i < 8; i++) {
            int r = (t >> 4) + i * 16;
            float nnr = g_nnr[row0 + r];
            float4 v = *(const float4*)&sOut[r * PGS + c4 * 4];
            v.x = v.x * nnr + b0;
            v.y = v.y * nnr + b1;
            v.z = v.z * nnr + b2;
            v.w = v.w * nnr + b3;
            *(float4*)&g_out2[(size_t)(row0 + r) * CMID + c4 * 4] = v;
            cs[0] += v.x; cq[0] += v.x * v.x;
            cs[1] += v.y; cq[1] += v.y * v.y;
            cs[2] += v.z; cq[2] += v.z * v.z;
            cs[3] += v.w; cq[3] += v.w * v.w;
        }
#pragma unroll
        for (int j = 0; j < 4; j++) {
            atomicAdd(&s_stats[c4 * 4 + j], cs[j]);
            atomicAdd(&s_stats[64 + c4 * 4 + j], cq[j]);
        }
    }
    __syncthreads();
    if (t < 64) {
        atomicAdd(&g_sum2[t], (double)s_stats[t]);
        atomicAdd(&g_sq2[t], (double)s_stats[64 + t]);
    }
}

// ---- GEMM2 (WMMA bf16 hi/lo): y = leaky(GN2(out2)) @ W2 + b2 ; GN3 stats ----
#define G2AS 72
#define G2BS 264
#define G2_SMEM (86016 + 2048 + 512)

__global__ __launch_bounds__(256) void k_gemm2(const float* __restrict__ W2,
                                               const float* __restrict__ b2,
                                               const float* __restrict__ gg,
                                               const float* __restrict__ gb) {
    extern __shared__ __nv_bfloat16 sb2[];
    __nv_bfloat16* sAhi = sb2;
    __nv_bfloat16* sAlo = sb2 + 4608;
    __nv_bfloat16* sBhi = sb2 + 9216;
    __nv_bfloat16* sBlo = sb2 + 26112;
    float* s_stats = (float*)((char*)sb2 + 86016);
    float* s_a2 = (float*)((char*)sb2 + 86016 + 2048);
    float* s_b2 = s_a2 + 64;
    float* sOut = (float*)sb2;

    int t = threadIdx.x;
    int warp = t >> 5;
    int wr = warp >> 2, wc = warp & 3;
    int row0 = blockIdx.x * 64;
    s_stats[t] = 0.f; s_stats[t + 256] = 0.f;
    if (t < 64) {
        int g = t >> 1;
        double s = g_sum2[g * 2] + g_sum2[g * 2 + 1];
        double q = g_sq2[g * 2] + g_sq2[g * 2 + 1];
        double cnt = 2.0 * (double)NPTS;
        double mean = s / cnt;
        double var = q / cnt - mean * mean;
        float inv = rsqrtf((float)var + EPSV);
        float av = gg[t] * inv;
        s_a2[t] = av;
        s_b2[t] = gb[t] - (float)mean * av;
    }
    __syncthreads();

#pragma unroll
    for (int i = 0; i < 4; i++) {
        int e = t + i * 256;
        int r = e >> 4, j = e & 15;
        float4 v = *(const float4*)&g_out2[(size_t)(row0 + r) * CMID + j * 4];
        float a0 = s_a2[j * 4 + 0], a1 = s_a2[j * 4 + 1], a2 = s_a2[j * 4 + 2], a3 = s_a2[j * 4 + 3];
        float c0 = s_b2[j * 4 + 0], c1 = s_b2[j * 4 + 1], c2 = s_b2[j * 4 + 2], c3 = s_b2[j * 4 + 3];
        v.x = a0 * v.x + c0; v.x = v.x >= 0.f ? v.x : SLOPE * v.x;
        v.y = a1 * v.y + c1; v.y = v.y >= 0.f ? v.y : SLOPE * v.y;
        v.z = a2 * v.z + c2; v.z = v.z >= 0.f ? v.z : SLOPE * v.z;
        v.w = a3 * v.w + c3; v.w = v.w >= 0.f ? v.w : SLOPE * v.w;
        uint32_t h0, l0, h1, l1;
        split2(v.x, v.y, h0, l0);
        split2(v.z, v.w, h1, l1);
        *(uint2*)&sAhi[r * G2AS + j * 4] = make_uint2(h0, h1);
        *(uint2*)&sAlo[r * G2AS + j * 4] = make_uint2(l0, l1);
    }
#pragma unroll
    for (int i = 0; i < 16; i++) {
        int e = t + i * 256;
        int r = e >> 6, j = e & 63;
        float4 v = *(const float4*)&W2[(size_t)r * COUT + j * 4];
        uint32_t h0, l0, h1, l1;
        split2(v.x, v.y, h0, l0);
        split2(v.z, v.w, h1, l1);
        *(uint2*)&sBhi[r * G2BS + j * 4] = make_uint2(h0, h1);
        *(uint2*)&sBlo[r * G2BS + j * 4] = make_uint2(l0, l1);
    }
    __syncthreads();

    wmma::fragment<wmma::accumulator, 16, 16, 16, float> acc[2][4];
#pragma unroll
    for (int i = 0; i < 2; i++)
#pragma unroll
        for (int j = 0; j < 4; j++) wmma::fill_fragment(acc[i][j], 0.0f);

#pragma unroll
    for (int kk = 0; kk < 4; kk++) {
        wmma::fragment<wmma::matrix_a, 16, 16, 16, __nv_bfloat16, wmma::row_major> a_hi[2], a_lo[2];
        wmma::fragment<wmma::matrix_b, 16, 16, 16, __nv_bfloat16, wmma::row_major> b_hi[4], b_lo[4];
#pragma unroll
        for (int i = 0; i < 2; i++) {
            wmma::load_matrix_sync(a_hi[i], &sAhi[(wr * 32 + i * 16) * G2AS + kk * 16], G2AS);
            wmma::load_matrix_sync(a_lo[i], &sAlo[(wr * 32 + i * 16) * G2AS + kk * 16], G2AS);
        }
#pragma unroll
        for (int j = 0; j < 4; j++) {
            wmma::load_matrix_sync(b_hi[j], &sBhi[(kk * 16) * G2BS + wc * 64 + j * 16], G2BS);
            wmma::load_matrix_sync(b_lo[j], &sBlo[(kk * 16) * G2BS + wc * 64 + j * 16], G2BS);
        }
#pragma unroll
        for (int i = 0; i < 2; i++)
#pragma unroll
            for (int j = 0; j < 4; j++) {
                wmma::mma_sync(acc[i][j], a_hi[i], b_hi[j], acc[i][j]);
                wmma::mma_sync(acc[i][j], a_lo[i], b_hi[j], acc[i][j]);
                wmma::mma_sync(acc[i][j], a_hi[i], b_lo[j], acc[i][j]);
            }
    }

    __syncthreads();
#pragma unroll
    for (int i = 0; i < 2; i++)
#pragma unroll
        for (int j = 0; j < 4; j++)
            wmma::store_matrix_sync(&sOut[(wr * 32 + i * 16) * G2BS + wc * 64 + j * 16],
                                    acc[i][j], G2BS, wmma::mem_row_major);
    __syncthreads();

    {
        int c4 = t & 63;
        float b0 = b2[c4 * 4 + 0], b1 = b2[c4 * 4 + 1];
        float bb2 = b2[c4 * 4 + 2], b3 = b2[c4 * 4 + 3];
        float cs[4] = {0, 0, 0, 0}, cq[4] = {0, 0, 0, 0};
#pragma unroll
        for (int i = 0; i < 16; i++) {
            int r = (t >> 6) + i * 4;
            float4 v = *(const float4*)&sOut[r * G2BS + c4 * 4];
            v.x += b0; v.y += b1; v.z += bb2; v.w += b3;
            *(float4*)&g_y[(size_t)(row0 + r) * COUT + c4 * 4] = v;
            cs[0] += v.x; cq[0] += v.x * v.x;
            cs[1] += v.y; cq[1] += v.y * v.y;
            cs[2] += v.z; cq[2] += v.z * v.z;
            cs[3] += v.w; cq[3] += v.w * v.w;
        }
#pragma unroll
        for (int j = 0; j < 4; j++) {
            atomicAdd(&s_stats[c4 * 4 + j], cs[j]);
            atomicAdd(&s_stats[256 + c4 * 4 + j], cq[j]);
        }
    }
    __syncthreads();
    atomicAdd(&g_sum3[t], (double)s_stats[t]);
    atomicAdd(&g_sq3[t], (double)s_stats[256 + t]);
}

// ---- final: out = leaky(GN3(y) + s_feats), inline GN3 finalize, MLP-8 ----
__global__ __launch_bounds__(256) void k_final(const float* __restrict__ sf,
                                               const float* __restrict__ g2f,
                                               const float* __restrict__ beta2f,
                                               float* __restrict__ out) {
    __shared__ float s_a[256], s_b[256];
    int t = threadIdx.x;
    {
        int g = t >> 3;
        double s = 0.0, q = 0.0;
#pragma unroll
        for (int i = 0; i < 8; i++) { s += g_sum3[g * 8 + i]; q += g_sq3[g * 8 + i]; }
        double cnt = 8.0 * (double)NPTS;
        double mean = s / cnt;
        double var = q / cnt - mean * mean;
        float inv = rsqrtf((float)var + EPSV);
        float av = g2f[t] * inv;
        s_a[t] = av;
        s_b[t] = beta2f[t] - (float)mean * av;
    }
    __syncthreads();
    int base = blockIdx.x * 1024 + t;
    int c = (base & 63) * 4;
    float a0 = s_a[c + 0], a1 = s_a[c + 1], a2 = s_a[c + 2], a3 = s_a[c + 3];
    float b0 = s_b[c + 0], b1 = s_b[c + 1], b2 = s_b[c + 2], b3 = s_b[c + 3];
    float4 y[4], s[4];
#pragma unroll
    for (int u = 0; u < 4; u++) {
        y[u] = ((const float4*)g_y)[base + u * 256];
        s[u] = ((const float4*)sf)[base + u * 256];
    }
#pragma unroll
    for (int u = 0; u < 4; u++) {
        float4 r;
        r.x = a0 * y[u].x + b0 + s[u].x;
        r.y = a1 * y[u].y + b1 + s[u].y;
        r.z = a2 * y[u].z + b2 + s[u].z;
        r.w = a3 * y[u].w + b3 + s[u].w;
        r.x = r.x >= 0.f ? r.x : SLOPE * r.x;
        r.y = r.y >= 0.f ? r.y : SLOPE * r.y;
        r.z = r.z >= 0.f ? r.z : SLOPE * r.z;
        r.w = r.w >= 0.f ? r.w : SLOPE * r.w;
        ((float4*)out)[base + u * 256] = r;
    }
}

extern "C" void kernel_launch(void* const* d_in, const int* in_sizes, int n_in,
                              void* d_out, int out_size) {
    const float* s_feats  = (const float*)d_in[0];
    const float* q_points = (const float*)d_in[1];
    const float* s_points = (const float*)d_in[2];
    const int*   nbr      = (const int*)d_in[3];
    const float* W1       = (const float*)d_in[4];
    const float* b1       = (const float*)d_in[5];
    const float* g1       = (const float*)d_in[6];
    const float* beta1    = (const float*)d_in[7];
    const float* kpw      = (const float*)d_in[8];
    const float* kpb      = (const float*)d_in[9];
    const float* kpts     = (const float*)d_in[10];
    const float* gg       = (const float*)d_in[11];
    const float* gb       = (const float*)d_in[12];
    const float* W2       = (const float*)d_in[13];
    const float* b2       = (const float*)d_in[14];
    const float* g2       = (const float*)d_in[15];
    const float* beta2    = (const float*)d_in[16];
    float* out = (float*)d_out;

    cudaFuncSetAttribute(k_gemm1, cudaFuncAttributeMaxDynamicSharedMemorySize, G1_SMEM);
    cudaFuncSetAttribute(k_pgemm, cudaFuncAttributeMaxDynamicSharedMemorySize, PG_SMEM);
    cudaFuncSetAttribute(k_gemm2, cudaFuncAttributeMaxDynamicSharedMemorySize, G2_SMEM);

    k_prep<<<240, 256>>>(kpw);
    k_gemm1<<<NPTS / 128, 256, G1_SMEM>>>(s_feats, W1, b1);
    k_apply1<<<NPTS * CMID / 4 / 1024, 256>>>(g1, beta1);
    k_gather<<<NPTS / 8, 256>>>(q_points, s_points, nbr, kpts);
    k_pgemm<<<NPTS / 128, 256, PG_SMEM>>>(kpb);
    k_gemm2<<<NPTS / 64, 256, G2_SMEM>>>(W2, b2, gg, gb);
    k_final<<<NPTS * COUT / 4 / 1024, 256>>>(s_feats, g2, beta2, out);
}